// round 1
// baseline (speedup 1.0000x reference)
#include <cuda_runtime.h>
#include <cstdint>

// Problem constants (fixed by setup_inputs)
#define BATCH 4096
#define VSZ   256
#define NU    129   // U+1 options per step
#define SKIP  25

// Strictly monotone float -> uint32 key (order-preserving bijection)
__device__ __forceinline__ unsigned fkey(float f) {
    unsigned u = __float_as_uint(f);
    return (u & 0x80000000u) ? ~u : (u | 0x80000000u);
}
// Exact inverse
__device__ __forceinline__ float fkey_inv(unsigned k) {
    return __uint_as_float((k & 0x80000000u) ? (k ^ 0x80000000u) : ~k);
}

__global__ void __launch_bounds__(256, 8)
greedy_matching_kernel(const float* __restrict__ x, float* __restrict__ out) {
    const int warp = (blockIdx.x * blockDim.x + threadIdx.x) >> 5;
    const int lane = threadIdx.x & 31;
    if (warp >= BATCH) return;

    const float* __restrict__ base = x + (size_t)warp * VSZ * NU;
    float* __restrict__ pi_out = out + BATCH + (size_t)warp * VSZ;

    // Steps t < SKIP: sel = 0, weight 0, no mask change. Just emit zeros.
    for (int t = lane; t < SKIP; t += 32) pi_out[t] = 0.0f;

    // Per-lane availability mask: bit k -> option j = lane + 32*k (k=0..3);
    // lane 0 additionally owns j = 128 via bit 4. Bit set = already matched.
    unsigned mask = 0u;
    float size = 0.0f;

    const float* p = base + (size_t)SKIP * NU;

    // Prefetch first live row
    float v0 = p[lane];
    float v1 = p[32 + lane];
    float v2 = p[64 + lane];
    float v3 = p[96 + lane];
    float v4 = (lane == 0) ? p[128] : 0.0f;

    for (int t = SKIP; t < VSZ; ++t) {
        float c0 = v0, c1 = v1, c2 = v2, c3 = v3, c4 = v4;

        // Prefetch next row (loads independent of the sequential state)
        p += NU;
        if (t + 1 < VSZ) {
            v0 = p[lane];
            v1 = p[32 + lane];
            v2 = p[64 + lane];
            v3 = p[96 + lane];
            if (lane == 0) v4 = p[128];
        }

        if (lane == 0) c0 = 0.0f;  // skip option has weight forced to 0

        // Keys: masked entries -> 0 (strictly below key(0.0) = 0x80000000,
        // so the always-available skip option dominates them, matching the
        // reference's -1e30 fill).
        unsigned k0 = (mask & 1u) ? 0u : fkey(c0);
        unsigned k1 = (mask & 2u) ? 0u : fkey(c1);
        unsigned k2 = (mask & 4u) ? 0u : fkey(c2);
        unsigned k3 = (mask & 8u) ? 0u : fkey(c3);
        unsigned k4 = (lane == 0 && !(mask & 16u)) ? fkey(c4) : 0u;

        // Lane-local argmax, strict '>' keeps the smallest j on ties
        unsigned bk = k0; unsigned bj = (unsigned)lane;
        if (k1 > bk) { bk = k1; bj = (unsigned)(lane + 32); }
        if (k2 > bk) { bk = k2; bj = (unsigned)(lane + 64); }
        if (k3 > bk) { bk = k3; bj = (unsigned)(lane + 96); }
        if (k4 > bk) { bk = k4; bj = 128u; }

        // Warp argmax with first-index tie-break: REDUX max on key,
        // then REDUX min on index among holders of the max key.
        unsigned vmax = __reduce_max_sync(0xFFFFFFFFu, bk);
        unsigned cand = (bk == vmax) ? bj : 0xFFFFFFFFu;
        unsigned sel  = __reduce_min_sync(0xFFFFFFFFu, cand);

        // Chosen weight = exact inverse of the winning key (w[sel]; the
        // winner is never a masked entry). Same fp32 accumulation order
        // as the reference scan.
        size += fkey_inv(vmax);

        // Mark sel as matched (sel == 0 never exhausted)
        if (sel != 0u) {
            if (sel == 128u) {
                if (lane == 0) mask |= 16u;
            } else if ((sel & 31u) == (unsigned)lane) {
                mask |= 1u << (sel >> 5);
            }
        }

        if (lane == 0) pi_out[t] = (float)sel;
    }

    if (lane == 0) out[warp] = -size;
}

extern "C" void kernel_launch(void* const* d_in, const int* in_sizes, int n_in,
                              void* d_out, int out_size) {
    const float* x = (const float*)d_in[0];
    float* out = (float*)d_out;
    // One warp per batch element: 4096 warps -> 512 blocks x 256 threads
    greedy_matching_kernel<<<BATCH / 8, 256>>>(x, out);
}

// round 2
// speedup vs baseline: 1.3982x; 1.3982x over previous
#include <cuda_runtime.h>
#include <cstdint>
#include <math_constants.h>

#define BATCH 4096
#define VSZ   256
#define NU    129
#define SKIP  25
#define NEGINF (-CUDART_INF_F)

// Strictly monotone float -> uint32 key (order-preserving bijection)
__device__ __forceinline__ unsigned fkey(float f) {
    unsigned u = __float_as_uint(f);
    return u ^ ((unsigned)((int)u >> 31) | 0x80000000u);
}
// Exact inverse
__device__ __forceinline__ float fkey_inv(unsigned k) {
    unsigned m = (k & 0x80000000u) ? 0x80000000u : 0xFFFFFFFFu;
    return __uint_as_float(k ^ m);
}

__global__ void __launch_bounds__(256, 4)
greedy_matching_kernel(const float* __restrict__ x, float* __restrict__ out) {
    const int warp = (blockIdx.x * blockDim.x + threadIdx.x) >> 5;
    const int lane = threadIdx.x & 31;

    const float* __restrict__ base = x + (size_t)warp * (VSZ * NU);
    float* __restrict__ pi_out = out + BATCH + (size_t)warp * VSZ;

    // Steps t < SKIP: sel = 0, weight 0, no mask change.
    for (int t = lane; t < SKIP; t += 32) pi_out[t] = 0.0f;

    // Additive availability bias per owned option: 0.0f = available, -inf = matched.
    // Lane l owns j = l, l+32, l+64, l+96; j=128 owned by lane 0 (tier 4).
    float b0 = 0.f, b1 = 0.f, b2 = 0.f, b3 = 0.f;
    float b4 = (lane == 0) ? 0.f : NEGINF;
    const float z0 = (lane == 0) ? 0.f : 1.f;  // forces skip weight to 0 on lane 0
    const int l1 = lane + 32, l2 = lane + 64, l3 = lane + 96;
    const int l4 = (lane == 0) ? 128 : -1;
    float size = 0.f;

    // Ring of 3 prefetched rows (t, t+1, t+2). 231 live steps = 3 * 77.
    float a0,a1,a2,a3,a4, c0,c1,c2,c3,c4, e0,e1,e2,e3,e4;
    {
        const float* p = base + SKIP * NU;
        a0 = p[lane]; a1 = p[l1]; a2 = p[l2]; a3 = p[l3]; a4 = p[128];
        p += NU;
        c0 = p[lane]; c1 = p[l1]; c2 = p[l2]; c3 = p[l3]; c4 = p[128];
        p += NU;
        e0 = p[lane]; e1 = p[l1]; e2 = p[l2]; e3 = p[l3]; e4 = p[128];
    }

    // Stage: consume buffer (row T), immediately refill it with row T+3
    // (registers are dead right after the f-computation -> max load-to-use
    // distance ~3 stages), then do the reduction/state update.
#define STAGE(B0,B1,B2,B3,B4, T)                                               \
    do {                                                                       \
        float f0 = fmaf(B0, z0, b0);                                           \
        float f1 = B1 + b1;                                                    \
        float f2 = B2 + b2;                                                    \
        float f3 = B3 + b3;                                                    \
        float f4 = B4 + b4;                                                    \
        /* refill: row min(T+3, VSZ-1) (clamp avoids OOB on the tail) */       \
        {                                                                      \
            int r = (T) + 3; r = (r < VSZ - 1) ? r : (VSZ - 1);                \
            const float* __restrict__ q = base + (size_t)r * NU;               \
            B0 = q[lane]; B1 = q[l1]; B2 = q[l2]; B3 = q[l3]; B4 = q[128];     \
        }                                                                      \
        float lm = fmaxf(fmaxf(fmaxf(f0, f1), fmaxf(f2, f3)), f4);             \
        unsigned gk = __reduce_max_sync(0xFFFFFFFFu, fkey(lm));                \
        float gf = fkey_inv(gk);                                               \
        size += gf;                                                            \
        unsigned cand = (f0 == gf) ? (unsigned)lane                            \
                      : (f1 == gf) ? (unsigned)l1                              \
                      : (f2 == gf) ? (unsigned)l2                              \
                      : (f3 == gf) ? (unsigned)l3                              \
                      : (f4 == gf) ? 128u : 0xFFFFFFFFu;                       \
        int s = (int)__reduce_min_sync(0xFFFFFFFFu, cand);                     \
        if (s != 0) {                                                          \
            if (s == lane) b0 = NEGINF;                                        \
            if (s == l1)  b1 = NEGINF;                                         \
            if (s == l2)  b2 = NEGINF;                                         \
            if (s == l3)  b3 = NEGINF;                                         \
            if (s == l4)  b4 = NEGINF;                                         \
        }                                                                      \
        if (lane == 0) pi_out[T] = (float)s;                                   \
    } while (0)

#pragma unroll 1
    for (int t = SKIP; t < VSZ; t += 3) {
        STAGE(a0, a1, a2, a3, a4, t);
        STAGE(c0, c1, c2, c3, c4, t + 1);
        STAGE(e0, e1, e2, e3, e4, t + 2);
    }

    if (lane == 0) out[warp] = -size;
}

extern "C" void kernel_launch(void* const* d_in, const int* in_sizes, int n_in,
                              void* d_out, int out_size) {
    const float* x = (const float*)d_in[0];
    float* out = (float*)d_out;
    greedy_matching_kernel<<<BATCH / 8, 256>>>(x, out);
}

// round 3
// speedup vs baseline: 1.4318x; 1.0240x over previous
#include <cuda_runtime.h>
#include <cstdint>
#include <math_constants.h>

#define BATCH 4096
#define VSZ   256
#define NU    129
#define SKIP  25
#define NEGINF (-CUDART_INF_F)

#define ROW_BYTES   (NU * 4)                 // 516
#define GROUP_ROWS  4
#define GROUP_BYTES (ROW_BYTES * GROUP_ROWS) // 2064 (16B multiple)
#define FIRST_ROW   24                       // 516*24 is 16B-aligned; rows 24..255 = 58 groups
#define NGROUPS     58
#define NSLOTS      3
#define WPB         4                        // warps per block

// Strictly monotone float -> uint32 key (order-preserving bijection) + exact inverse
__device__ __forceinline__ unsigned fkey(float f) {
    unsigned u = __float_as_uint(f);
    return u ^ ((unsigned)((int)u >> 31) | 0x80000000u);
}
__device__ __forceinline__ float fkey_inv(unsigned k) {
    unsigned m = (k & 0x80000000u) ? 0x80000000u : 0xFFFFFFFFu;
    return __uint_as_float(k ^ m);
}

__device__ __forceinline__ uint32_t smem_u32(const void* p) {
    uint32_t a;
    asm("{ .reg .u64 t; cvta.to.shared.u64 t, %1; cvt.u32.u64 %0, t; }" : "=r"(a) : "l"(p));
    return a;
}
__device__ __forceinline__ void mbar_init(uint32_t mbar, uint32_t cnt) {
    asm volatile("mbarrier.init.shared.b64 [%0], %1;" :: "r"(mbar), "r"(cnt) : "memory");
}
__device__ __forceinline__ void mbar_expect_tx(uint32_t mbar, uint32_t bytes) {
    asm volatile("mbarrier.arrive.expect_tx.shared.b64 _, [%0], %1;"
                 :: "r"(mbar), "r"(bytes) : "memory");
}
__device__ __forceinline__ void bulk_g2s(uint32_t dst, const void* src, uint32_t bytes, uint32_t mbar) {
    asm volatile("cp.async.bulk.shared::cta.global.mbarrier::complete_tx::bytes [%0], [%1], %2, [%3];"
                 :: "r"(dst), "l"(src), "r"(bytes), "r"(mbar) : "memory");
}
__device__ __forceinline__ void mbar_wait(uint32_t mbar, uint32_t parity) {
    uint32_t done;
    asm volatile("{\n\t.reg .pred p;\n\t"
                 "mbarrier.try_wait.parity.acquire.cta.shared::cta.b64 p, [%1], %2;\n\t"
                 "selp.b32 %0, 1, 0, p;\n\t}"
                 : "=r"(done) : "r"(mbar), "r"(parity) : "memory");
    if (!done) {
        asm volatile("{\n\t.reg .pred P1;\n\t"
                     "W_%=:\n\t"
                     "mbarrier.try_wait.parity.acquire.cta.shared::cta.b64 P1, [%0], %1, 0x989680;\n\t"
                     "@P1 bra.uni D_%=;\n\t"
                     "bra.uni W_%=;\n\t"
                     "D_%=:\n\t}"
                     :: "r"(mbar), "r"(parity) : "memory");
    }
}

__global__ void __launch_bounds__(128, 7)
greedy_matching_kernel(const float* __restrict__ x, float* __restrict__ out) {
    __shared__ __align__(128) unsigned char sbuf[WPB][NSLOTS][GROUP_BYTES];
    __shared__ __align__(8)   unsigned long long smbar[WPB][NSLOTS];

    const int wib  = threadIdx.x >> 5;
    const int lane = threadIdx.x & 31;
    const int warp = blockIdx.x * WPB + wib;

    const float* __restrict__ base = x + (size_t)warp * (VSZ * NU);
    float* __restrict__ pi_out = out + BATCH + (size_t)warp * VSZ;

    const uint32_t sb  = smem_u32(&sbuf[wib][0][0]);
    const uint32_t mbb = smem_u32(&smbar[wib][0]);

    // lane 0: init per-warp mbarriers, fence, prime the 3-slot ring (groups 0..2)
    if (lane == 0) {
        mbar_init(mbb + 0, 1);
        mbar_init(mbb + 8, 1);
        mbar_init(mbb + 16, 1);
        asm volatile("fence.proxy.async.shared::cta;" ::: "memory");
#pragma unroll
        for (int s = 0; s < NSLOTS; ++s) {
            mbar_expect_tx(mbb + 8u * s, GROUP_BYTES);
            bulk_g2s(sb + s * GROUP_BYTES,
                     base + (size_t)(FIRST_ROW + GROUP_ROWS * s) * NU,
                     GROUP_BYTES, mbb + 8u * s);
        }
    }
    __syncwarp();

    // Skip phase: sel = 0, weight 0, no mask change.
    for (int t = lane; t < SKIP; t += 32) pi_out[t] = 0.0f;

    // Additive availability bias: 0 = available, -inf = matched.
    // Lane l owns j = l, l+32, l+64, l+96; j = 128 real only on lane 0.
    float b0 = 0.f, b1 = 0.f, b2 = 0.f, b3 = 0.f;
    float b4 = (lane == 0) ? 0.f : NEGINF;
    const float z0 = (lane == 0) ? 0.f : 1.f;  // forces skip weight to 0 on lane 0
    float size = 0.f;

    // One greedy step on smem row `rp` (129 floats), emitting pi[T].
#define STEP(rp, T)                                                            \
    do {                                                                       \
        float w0 = (rp)[lane];                                                 \
        float w1 = (rp)[lane + 32];                                            \
        float w2 = (rp)[lane + 64];                                            \
        float w3 = (rp)[lane + 96];                                            \
        float w4 = (rp)[128];                                                  \
        float f0 = fmaf(w0, z0, b0);                                           \
        float f1 = w1 + b1;                                                    \
        float f2 = w2 + b2;                                                    \
        float f3 = w3 + b3;                                                    \
        float f4 = w4 + b4;                                                    \
        float lm = fmaxf(fmaxf(fmaxf(f0, f1), fmaxf(f2, f3)), f4);             \
        unsigned gk = __reduce_max_sync(0xFFFFFFFFu, fkey(lm));                \
        float gf = fkey_inv(gk);                                               \
        size += gf;                                                            \
        unsigned cand = (f0 == gf) ? (unsigned)lane                            \
                      : (f1 == gf) ? (unsigned)(lane + 32)                     \
                      : (f2 == gf) ? (unsigned)(lane + 64)                     \
                      : (f3 == gf) ? (unsigned)(lane + 96)                     \
                      : (f4 == gf) ? 128u : 0xFFFFFFFFu;                       \
        int s = (int)__reduce_min_sync(0xFFFFFFFFu, cand);                     \
        int d = s - lane;                                                      \
        if (d == 0 && s != 0) b0 = NEGINF;                                     \
        if (d == 32)  b1 = NEGINF;                                             \
        if (d == 64)  b2 = NEGINF;                                             \
        if (d == 96)  b3 = NEGINF;                                             \
        if (d == 128) b4 = NEGINF;                                             \
        if (lane == 0) pi_out[T] = (float)s;                                   \
    } while (0)

    int stage = 0, phase = 0;

    // Group 0 (rows 24..27): row 24 is in the skip phase, consume rows 1..3.
    {
        mbar_wait(mbb + 8u * stage, phase);
        const unsigned char* sp = &sbuf[wib][stage][0];
        STEP((const float*)(sp + 1 * ROW_BYTES), 25);
        STEP((const float*)(sp + 2 * ROW_BYTES), 26);
        STEP((const float*)(sp + 3 * ROW_BYTES), 27);
        if (lane == 0) {  // refill with group 3
            mbar_expect_tx(mbb + 8u * stage, GROUP_BYTES);
            bulk_g2s(sb + stage * GROUP_BYTES,
                     base + (size_t)(FIRST_ROW + GROUP_ROWS * NSLOTS) * NU,
                     GROUP_BYTES, mbb + 8u * stage);
        }
        if (++stage == NSLOTS) { stage = 0; phase ^= 1; }
    }

    // Groups 1..57: 4 steps each; refill group g+3 while g+3 < 58.
#pragma unroll 1
    for (int g = 1; g < NGROUPS; ++g) {
        mbar_wait(mbb + 8u * stage, phase);
        const unsigned char* sp = &sbuf[wib][stage][0];
        const int t0 = FIRST_ROW + GROUP_ROWS * g;
        STEP((const float*)(sp + 0 * ROW_BYTES), t0 + 0);
        STEP((const float*)(sp + 1 * ROW_BYTES), t0 + 1);
        STEP((const float*)(sp + 2 * ROW_BYTES), t0 + 2);
        STEP((const float*)(sp + 3 * ROW_BYTES), t0 + 3);
        if (lane == 0 && g + NSLOTS < NGROUPS) {
            mbar_expect_tx(mbb + 8u * stage, GROUP_BYTES);
            bulk_g2s(sb + stage * GROUP_BYTES,
                     base + (size_t)(FIRST_ROW + GROUP_ROWS * (g + NSLOTS)) * NU,
                     GROUP_BYTES, mbb + 8u * stage);
        }
        if (++stage == NSLOTS) { stage = 0; phase ^= 1; }
    }

    if (lane == 0) out[warp] = -size;
}

extern "C" void kernel_launch(void* const* d_in, const int* in_sizes, int n_in,
                              void* d_out, int out_size) {
    const float* x = (const float*)d_in[0];
    float* out = (float*)d_out;
    greedy_matching_kernel<<<BATCH / WPB, 128>>>(x, out);
}